// round 16
// baseline (speedup 1.0000x reference)
#include <cuda_runtime.h>
#include <cuda_bf16.h>
#include <stdint.h>

#define CN 128      // channels (= GEMM N = K)
#define NGR 128     // num graphs
#define TM 64       // tile rows per block
#define NT 512      // threads per block (16 warps)
#define CSP 132     // C staging pitch (floats)
#define SROWS 512
#define EPSV 1e-5f

// ---- smem byte offsets (swizzled tiles: 256 B per row) ----
#define ATILE (TM * 256)                  // 16384
#define BTILE (CN * 256)                  // 32768
#define OFF_AH   0
#define OFF_AL   (OFF_AH + ATILE)         // 16384
#define OFF_BH   (OFF_AL + ATILE)         // 32768
#define OFF_META (OFF_BH + BTILE)         // 65536
#define OFF_CS   0                        // C staging aliases A+Bh (64*132*4 = 33792 <= 65536)

// 16B-chunk XOR swizzle within a 256B row
__device__ __forceinline__ uint32_t swz(int row, int chunk) {
    return (uint32_t)(row * 256 + ((chunk ^ (row & 7)) << 4));
}

// ---- W split into bf16 hi/lo, transposed (g[n][k] = split(W[k][n])) ----
__device__ __align__(16) __nv_bfloat16 g_w1h[CN*CN];
__device__ __align__(16) __nv_bfloat16 g_w1l[CN*CN];
__device__ __align__(16) __nv_bfloat16 g_w2h[CN*CN];
__device__ __align__(16) __nv_bfloat16 g_w2l[CN*CN];

// ---- stats scratch ----
__device__ float g_sum1[NGR*CN];
__device__ float g_sq1 [NGR*CN];
__device__ float g_sum2[NGR*CN];
__device__ float g_sq2 [NGR*CN];
__device__ float g_scale1[NGR*CN];
__device__ float g_shift1[NGR*CN];
__device__ float g_scale2[NGR*CN];
__device__ float g_shift2[NGR*CN];
__device__ int   g_cnt1[NGR];
__device__ int   g_cnt2[NGR];

// ---- helpers ----
__device__ __forceinline__ uint32_t smem_u32(const void* p) {
    uint32_t a;
    asm("{ .reg .u64 t; cvta.to.shared.u64 t, %1; cvt.u32.u64 %0, t; }" : "=r"(a) : "l"(p));
    return a;
}
__device__ __forceinline__ void ldm_x4(uint32_t* r, uint32_t addr) {
    asm volatile("ldmatrix.sync.aligned.m8n8.x4.shared.b16 {%0,%1,%2,%3}, [%4];"
                 : "=r"(r[0]), "=r"(r[1]), "=r"(r[2]), "=r"(r[3]) : "r"(addr));
}
__device__ __forceinline__ void mma_bf16(float* d, const uint32_t* a, uint32_t b0, uint32_t b1) {
    asm volatile("mma.sync.aligned.m16n8k16.row.col.f32.bf16.bf16.f32 "
                 "{%0,%1,%2,%3}, {%4,%5,%6,%7}, {%8,%9}, {%0,%1,%2,%3};"
                 : "+f"(d[0]), "+f"(d[1]), "+f"(d[2]), "+f"(d[3])
                 : "r"(a[0]), "r"(a[1]), "r"(a[2]), "r"(a[3]), "r"(b0), "r"(b1));
}
__device__ __forceinline__ void red4(float* p, float x, float y, float z, float w) {
    asm volatile("red.global.add.v4.f32 [%0], {%1,%2,%3,%4};"
                 :: "l"(p), "f"(x), "f"(y), "f"(z), "f"(w) : "memory");
}
__device__ __forceinline__ uint32_t b2u(__nv_bfloat162 h) {
    return *reinterpret_cast<uint32_t*>(&h);
}

// ================= small kernels =================
__global__ void zero_stats_kernel() {
    int i = blockIdx.x * blockDim.x + threadIdx.x;
    if (i < NGR*CN) { g_sum1[i]=0.f; g_sq1[i]=0.f; g_sum2[i]=0.f; g_sq2[i]=0.f; }
    if (i < NGR)    { g_cnt1[i]=0;   g_cnt2[i]=0; }
}

__global__ void count_kernel(const int* __restrict__ b, int n, int which) {
    __shared__ int s[NGR];
    int* cnt = which ? g_cnt2 : g_cnt1;
    for (int i = threadIdx.x; i < NGR; i += blockDim.x) s[i] = 0;
    __syncthreads();
    for (long i = (long)blockIdx.x*blockDim.x + threadIdx.x; i < n; i += (long)gridDim.x*blockDim.x)
        atomicAdd(&s[b[i]], 1);
    __syncthreads();
    for (int i = threadIdx.x; i < NGR; i += blockDim.x) if (s[i]) atomicAdd(&cnt[i], s[i]);
}

// split W1/W2 into bf16 hi/lo, transposed: g_w*h[n*CN+k] = bf16split(W[k*CN+n])
__global__ void wconvert_kernel(const float* __restrict__ W1, const float* __restrict__ W2) {
    int idx = blockIdx.x * 256 + threadIdx.x;   // 2*16384 total
    int sel = idx >> 14;
    int e   = idx & 16383;
    int k = e >> 7, nn = e & 127;
    const float* W = sel ? W2 : W1;
    float x = W[k*CN + nn];
    __nv_bfloat16 h = __float2bfloat16(x);
    __nv_bfloat16 l = __float2bfloat16(x - __bfloat162float(h));
    if (sel) { g_w2h[nn*CN+k] = h; g_w2l[nn*CN+k] = l; }
    else     { g_w1h[nn*CN+k] = h; g_w1l[nn*CN+k] = l; }
}

// ================= fused mma.sync GEMM + scatter =================
// C[64x128] = A_tile @ W via 3-term bf16-split mma.sync (AhWh + AlWh + AhWl).
// Bh staged in smem (ldmatrix); Bl fragments read directly via __ldg (L1-resident).
// smem 65.5KB -> 3 blocks/SM, 512 threads each (deep phase overlap).
template<int DEG, bool NORM>
__global__ __launch_bounds__(NT) void fused_mma_scatter(
    const float* __restrict__ A,
    const int* __restrict__ rows, const float* __restrict__ vals,
    float* __restrict__ agg,
    const int* __restrict__ batch, float* __restrict__ wb_out, int n)
{
    extern __shared__ char smem[];
    const uint32_t sb = smem_u32(smem);
    const int tid = threadIdx.x;
    const int wid = tid >> 5, lane = tid & 31;
    const int j0  = blockIdx.x * TM;
    const int nrow = min(TM, n - j0);

    const __nv_bfloat16* wth = NORM ? g_w2h : g_w1h;
    const __nv_bfloat16* wtl = NORM ? g_w2l : g_w1l;

    // ---- load A tile, (optional norm + output write), split to bf16 hi/lo
    {
        const float4* A4 = (const float4*)A;
        for (int i = tid; i < TM*32; i += NT) {
            int r = i >> 5, cq = i & 31;        // covers k = cq*4 .. cq*4+3
            float4 v = make_float4(0.f,0.f,0.f,0.f);
            if (r < nrow) {
                long idx = (long)(j0 + r) * 32 + cq;
                v = __ldcs(&A4[idx]);
                if (NORM) {
                    int g = batch[j0 + r];
                    float4 a = ((const float4*)g_scale1)[g*32 + cq];
                    float4 b = ((const float4*)g_shift1)[g*32 + cq];
                    v.x = v.x*a.x + b.x; v.y = v.y*a.y + b.y;
                    v.z = v.z*a.z + b.z; v.w = v.w*a.w + b.w;
                }
                __stcs(&((float4*)wb_out)[idx], v);
            }
            __nv_bfloat162 h01 = __float22bfloat162_rn(make_float2(v.x, v.y));
            __nv_bfloat162 h23 = __float22bfloat162_rn(make_float2(v.z, v.w));
            float2 f01 = __bfloat1622float2(h01);
            float2 f23 = __bfloat1622float2(h23);
            __nv_bfloat162 l01 = __float22bfloat162_rn(make_float2(v.x - f01.x, v.y - f01.y));
            __nv_bfloat162 l23 = __float22bfloat162_rn(make_float2(v.z - f23.x, v.w - f23.y));
            uint32_t off = swz(r, cq >> 1) + (uint32_t)(cq & 1) * 8;
            *(uint2*)(smem + OFF_AH + off) = make_uint2(b2u(h01), b2u(h23));
            *(uint2*)(smem + OFF_AL + off) = make_uint2(b2u(l01), b2u(l23));
        }
    }
    // ---- stage B hi = W^T hi (bf16 [n][k]) into swizzled smem
    for (int i = tid; i < CN*16; i += NT) {
        int nn = i >> 4, q = i & 15;           // q = 16B chunk index
        *(uint4*)(smem + OFF_BH + swz(nn, q)) = *(const uint4*)&wth[nn*CN + q*8];
    }
    // ---- stage scatter metadata
    int*   s_rows = (int*)(smem + OFF_META);
    float* s_vals = (float*)(smem + OFF_META + TM*DEG*4);
    for (int i = tid; i < nrow*DEG; i += NT) {
        long e = (long)j0*DEG + i;
        s_rows[i] = rows[e];
        s_vals[i] = vals[e];
    }
    __syncthreads();

    // ---- warp MMA: 16 warps; warp (wid&3) owns rows 16*(wid&3).., (wid>>2) owns 32-col group
    float acc[16];
#pragma unroll
    for (int i = 0; i < 16; i++) acc[i] = 0.f;
    {
        const int rgrp = (wid & 3) * 16;
        const int cgrp = (wid >> 2) * 32;
        const int sub = lane >> 3, l8 = lane & 7;
        const int ksub = sub >> 1;
        const int arow = rgrp + l8 + (sub & 1) * 8;
        const uint32_t aterm = (uint32_t)(arow * 256), ax = (uint32_t)(arow & 7);
        const int lq = lane >> 2, lr2 = (lane & 3) * 2;   // B-fragment lane coords
#pragma unroll
        for (int ks = 0; ks < 8; ks++) {       // k = 16*ks
            const int chunk = 2*ks + ksub;
            uint32_t ah[4], al[4];
            ldm_x4(ah, sb + OFF_AH + aterm + (((uint32_t)chunk ^ ax) << 4));
            ldm_x4(al, sb + OFF_AL + aterm + (((uint32_t)chunk ^ ax) << 4));
            const int kb = ks*16 + lr2;
#pragma unroll
            for (int np = 0; np < 2; np++) {   // n-tile pair: cols cgrp+16*np ..+15
                const int c0 = cgrp + np*16;
                // B hi from smem via ldmatrix
                const int brow = c0 + l8 + (sub & 1) * 8;
                uint32_t bh[4];
                ldm_x4(bh, sb + OFF_BH + (uint32_t)(brow * 256)
                               + (((uint32_t)chunk ^ (uint32_t)(brow & 7)) << 4));
                // B lo fragments direct from global (L1-resident W-lo)
                const __nv_bfloat16* p0 = &wtl[(c0 + lq)*CN + kb];
                const __nv_bfloat16* p1 = &wtl[(c0 + 8 + lq)*CN + kb];
                uint32_t bl0a = __ldg((const uint32_t*)p0);
                uint32_t bl0b = __ldg((const uint32_t*)(p0 + 8));
                uint32_t bl1a = __ldg((const uint32_t*)p1);
                uint32_t bl1b = __ldg((const uint32_t*)(p1 + 8));
                float* d0 = &acc[(2*np+0)*4];
                float* d1 = &acc[(2*np+1)*4];
                mma_bf16(d0, ah, bh[0], bh[2]);
                mma_bf16(d0, al, bh[0], bh[2]);
                mma_bf16(d0, ah, bl0a, bl0b);
                mma_bf16(d1, ah, bh[1], bh[3]);
                mma_bf16(d1, al, bh[1], bh[3]);
                mma_bf16(d1, ah, bl1a, bl1b);
            }
        }
    }
    __syncthreads();   // A/Bh fully consumed -> C staging may overwrite

    // ---- write accumulators to smem C (fragment layout -> [row][col])
    float* Cs = (float*)(smem + OFF_CS);
    {
        const int rowt = (wid & 3)*16 + (lane >> 2);
        const int cbase = (wid >> 2)*32 + 2*(lane & 3);
#pragma unroll
        for (int nt = 0; nt < 4; nt++) {
            const int col = cbase + nt*8;
            *(float2*)&Cs[rowt*CSP + col]     = make_float2(acc[nt*4+0], acc[nt*4+1]);
            *(float2*)&Cs[(rowt+8)*CSP + col] = make_float2(acc[nt*4+2], acc[nt*4+3]);
        }
    }
    __syncthreads();

    // ---- scatter: one v4 global reduction per (entry, 4-channel group)
    const int total = nrow * DEG * 32;
    for (int idx = tid; idx < total; idx += NT) {
        int e = idx >> 5, q = idx & 31;
        int src = e / DEG;
        float v = s_vals[e];
        float4 y = *(const float4*)&Cs[src*CSP + q*4];
        float* p = agg + (long)s_rows[e]*CN + q*4;
        red4(p, v*y.x, v*y.y, v*y.z, v*y.w);
    }
}

// ================= GraphNorm stats / finalize / apply =================
// one warp = one row per iteration (float4 per lane); 8 rows in flight per block
__global__ void stats_kernel(const float* __restrict__ y, const int* __restrict__ batch,
                             int n, int which)
{
    float* sum = which ? g_sum2 : g_sum1;
    float* sq  = which ? g_sq2  : g_sq1;
    const int c4 = threadIdx.x & 31;       // float4 column group
    const int p  = threadIdx.x >> 5;       // row phase (0..7)
    int r0 = blockIdx.x * SROWS;
    int rend = min(r0 + SROWS, n);
    float4 rs = make_float4(0,0,0,0), rq = make_float4(0,0,0,0);
    int cur = -1;
    for (int r = r0 + p; r < rend; r += 8) {
        int g = batch[r];
        if (g != cur) {
            if (cur >= 0) {
                float* s = &sum[cur*CN + c4*4];
                float* t = &sq [cur*CN + c4*4];
                atomicAdd(s+0, rs.x); atomicAdd(s+1, rs.y); atomicAdd(s+2, rs.z); atomicAdd(s+3, rs.w);
                atomicAdd(t+0, rq.x); atomicAdd(t+1, rq.y); atomicAdd(t+2, rq.z); atomicAdd(t+3, rq.w);
            }
            cur = g;
            rs = make_float4(0,0,0,0); rq = make_float4(0,0,0,0);
        }
        float4 v = ((const float4*)y)[(long)r*32 + c4];
        rs.x += v.x; rs.y += v.y; rs.z += v.z; rs.w += v.w;
        rq.x += v.x*v.x; rq.y += v.y*v.y; rq.z += v.z*v.z; rq.w += v.w*v.w;
    }
    if (cur >= 0) {
        float* s = &sum[cur*CN + c4*4];
        float* t = &sq [cur*CN + c4*4];
        atomicAdd(s+0, rs.x); atomicAdd(s+1, rs.y); atomicAdd(s+2, rs.z); atomicAdd(s+3, rs.w);
        atomicAdd(t+0, rq.x); atomicAdd(t+1, rq.y); atomicAdd(t+2, rq.z); atomicAdd(t+3, rq.w);
    }
}

__global__ void finalize_kernel(const float* __restrict__ wgt, const float* __restrict__ bias,
                                const float* __restrict__ mscale, int which)
{
    int i = blockIdx.x*blockDim.x + threadIdx.x;
    if (i >= NGR*CN) return;
    const float* sum = which ? g_sum2 : g_sum1;
    const float* sq  = which ? g_sq2  : g_sq1;
    const int*   cnt = which ? g_cnt2 : g_cnt1;
    float* sc = which ? g_scale2 : g_scale1;
    float* sh = which ? g_shift2 : g_shift1;
    int g = i >> 7, c = i & (CN-1);
    float nf  = fmaxf((float)cnt[g], 1.f);
    float m   = sum[i] / nf;
    float ms  = m * mscale[c];
    float var = sq[i]/nf - 2.f*ms*m + ms*ms;
    float inv = rsqrtf(var + EPSV);
    float a   = wgt[c] * inv;
    sc[i] = a;
    sh[i] = bias[c] - ms * a;
}

__global__ void apply_norm_kernel(float* __restrict__ y, const int* __restrict__ batch, int n)
{
    long idx = (long)blockIdx.x*blockDim.x + threadIdx.x;
    if (idx >= (long)n*32) return;
    int r = (int)(idx >> 5); int cq = (int)(idx & 31);
    int g = batch[r];
    float4 v = ((float4*)y)[idx];
    float4 a = ((const float4*)g_scale2)[g*32+cq];
    float4 b = ((const float4*)g_shift2)[g*32+cq];
    v.x = v.x*a.x + b.x; v.y = v.y*a.y + b.y;
    v.z = v.z*a.z + b.z; v.w = v.w*a.w + b.w;
    ((float4*)y)[idx] = v;
}

// ================= launch =================
extern "C" void kernel_launch(void* const* d_in, const int* in_sizes, int n_in,
                              void* d_out, int out_size)
{
    const float* x0   = (const float*)d_in[0];
    const float* x1   = (const float*)d_in[1];
    const float* x2   = (const float*)d_in[2];
    const float* W1   = (const float*)d_in[3];
    const float* W2   = (const float*)d_in[4];
    const float* gn1w = (const float*)d_in[5];
    const float* gn1b = (const float*)d_in[6];
    const float* gn1m = (const float*)d_in[7];
    const float* gn2w = (const float*)d_in[8];
    const float* gn2b = (const float*)d_in[9];
    const float* gn2m = (const float*)d_in[10];
    const int*   i2r  = (const int*)d_in[11];
    const float* i2v  = (const float*)d_in[13];
    const int*   i1r  = (const int*)d_in[14];
    const float* i1v  = (const float*)d_in[16];
    const int*   bn   = (const int*)d_in[17];
    const int*   be   = (const int*)d_in[18];

    const int n0 = in_sizes[0] / CN;
    const int n1 = in_sizes[1] / CN;
    const int n2 = in_sizes[2] / CN;

    float* out_x0 = (float*)d_out;
    float* out_x1 = out_x0 + (size_t)n0 * CN;
    float* out_x2 = out_x1 + (size_t)n1 * CN;

    const int SM3 = OFF_META + TM*3*8;   // 67072
    const int SM2 = OFF_META + TM*2*8;   // 66560
    cudaFuncSetAttribute((const void*)fused_mma_scatter<3,false>,
                         cudaFuncAttributeMaxDynamicSharedMemorySize, SM3);
    cudaFuncSetAttribute((const void*)fused_mma_scatter<2,true>,
                         cudaFuncAttributeMaxDynamicSharedMemorySize, SM2);

    // residual pre-fill of outputs (x_2 copy fused into GEMM1's A-load)
    cudaMemcpyAsync(out_x0, x0, (size_t)n0*CN*sizeof(float), cudaMemcpyDeviceToDevice, 0);
    cudaMemcpyAsync(out_x1, x1, (size_t)n1*CN*sizeof(float), cudaMemcpyDeviceToDevice, 0);

    zero_stats_kernel<<<64, 256>>>();
    count_kernel<<<232, 256>>>(be, n1, 0);
    count_kernel<<<232, 256>>>(bn, n0, 1);
    wconvert_kernel<<<128, 256>>>(W1, W2);

    // layer 1: out_x1 += inc2 @ (x_2 @ W1); out_x2 = x_2 (fused copy)
    fused_mma_scatter<3,false><<<(n2+TM-1)/TM, NT, SM3>>>(
        x2, i2r, i2v, out_x1, nullptr, out_x2, n2);
    stats_kernel<<<(n1+SROWS-1)/SROWS, 256>>>(out_x1, be, n1, 0);
    finalize_kernel<<<64, 256>>>(gn1w, gn1b, gn1m, 0);

    // layer 2: normalize x_1_out in-flight, out_x0 += inc1 @ (x_1_out @ W2)
    fused_mma_scatter<2,true><<<(n1+TM-1)/TM, NT, SM2>>>(
        out_x1, i1r, i1v, out_x0, be, out_x1, n1);
    stats_kernel<<<(n0+SROWS-1)/SROWS, 256>>>(out_x0, bn, n0, 1);
    finalize_kernel<<<64, 256>>>(gn2w, gn2b, gn2m, 1);
    apply_norm_kernel<<<(int)(((long)n0*32 + 255)/256), 256>>>(out_x0, bn, n0);
}

// round 17
// speedup vs baseline: 1.2858x; 1.2858x over previous
#include <cuda_runtime.h>
#include <cuda_bf16.h>
#include <stdint.h>

#define CN 128      // channels (= GEMM N = K)
#define NGR 128     // num graphs
#define TM 64       // tile rows per block
#define CSP 132     // C staging pitch (floats)
#define SROWS 512
#define EPSV 1e-5f

// ---- smem byte offsets ----
// A tiles: 256B rows (full K).  B tiles: 128B rows (one 64-wide K-half at a time).
#define ATILE (TM * 256)                  // 16384
#define BTILE (CN * 128)                  // 16384 (one half, one precision)
#define OFF_AH   0
#define OFF_AL   (OFF_AH + ATILE)         // 16384
#define OFF_BH   (OFF_AL + ATILE)         // 32768
#define OFF_BL   (OFF_BH + BTILE)         // 49152
#define OFF_META (OFF_BL + BTILE)         // 65536
#define OFF_CS   0                        // C staging aliases A+B (64*132*4 = 33792)

// 16B-chunk XOR swizzles
__device__ __forceinline__ uint32_t swzA(int row, int chunk) {   // chunk 0..15
    return (uint32_t)(row * 256 + ((chunk ^ (row & 7)) << 4));
}
__device__ __forceinline__ uint32_t swzB(int row, int chunk) {   // chunk 0..7
    return (uint32_t)(row * 128 + ((chunk ^ (row & 7)) << 4));
}

// ---- W split into bf16 hi/lo, transposed (g[n][k] = split(W[k][n])) ----
__device__ __align__(16) __nv_bfloat16 g_w1h[CN*CN];
__device__ __align__(16) __nv_bfloat16 g_w1l[CN*CN];
__device__ __align__(16) __nv_bfloat16 g_w2h[CN*CN];
__device__ __align__(16) __nv_bfloat16 g_w2l[CN*CN];

// ---- stats scratch ----
__device__ float g_sum1[NGR*CN];
__device__ float g_sq1 [NGR*CN];
__device__ float g_sum2[NGR*CN];
__device__ float g_sq2 [NGR*CN];
__device__ float g_scale1[NGR*CN];
__device__ float g_shift1[NGR*CN];
__device__ float g_scale2[NGR*CN];
__device__ float g_shift2[NGR*CN];
__device__ int   g_cnt1[NGR];
__device__ int   g_cnt2[NGR];

// ---- helpers ----
__device__ __forceinline__ uint32_t smem_u32(const void* p) {
    uint32_t a;
    asm("{ .reg .u64 t; cvta.to.shared.u64 t, %1; cvt.u32.u64 %0, t; }" : "=r"(a) : "l"(p));
    return a;
}
__device__ __forceinline__ void ldm_x4(uint32_t* r, uint32_t addr) {
    asm volatile("ldmatrix.sync.aligned.m8n8.x4.shared.b16 {%0,%1,%2,%3}, [%4];"
                 : "=r"(r[0]), "=r"(r[1]), "=r"(r[2]), "=r"(r[3]) : "r"(addr));
}
__device__ __forceinline__ void mma_bf16(float* d, const uint32_t* a, uint32_t b0, uint32_t b1) {
    asm volatile("mma.sync.aligned.m16n8k16.row.col.f32.bf16.bf16.f32 "
                 "{%0,%1,%2,%3}, {%4,%5,%6,%7}, {%8,%9}, {%0,%1,%2,%3};"
                 : "+f"(d[0]), "+f"(d[1]), "+f"(d[2]), "+f"(d[3])
                 : "r"(a[0]), "r"(a[1]), "r"(a[2]), "r"(a[3]), "r"(b0), "r"(b1));
}
__device__ __forceinline__ unsigned short bfbits(__nv_bfloat16 h) {
    return *reinterpret_cast<unsigned short*>(&h);
}
__device__ __forceinline__ void red4(float* p, float x, float y, float z, float w) {
    asm volatile("red.global.add.v4.f32 [%0], {%1,%2,%3,%4};"
                 :: "l"(p), "f"(x), "f"(y), "f"(z), "f"(w) : "memory");
}

// ================= small kernels =================
__global__ void zero_stats_kernel() {
    int i = blockIdx.x * blockDim.x + threadIdx.x;
    if (i < NGR*CN) { g_sum1[i]=0.f; g_sq1[i]=0.f; g_sum2[i]=0.f; g_sq2[i]=0.f; }
    if (i < NGR)    { g_cnt1[i]=0;   g_cnt2[i]=0; }
}

__global__ void count_kernel(const int* __restrict__ b, int n, int which) {
    __shared__ int s[NGR];
    int* cnt = which ? g_cnt2 : g_cnt1;
    for (int i = threadIdx.x; i < NGR; i += blockDim.x) s[i] = 0;
    __syncthreads();
    for (long i = (long)blockIdx.x*blockDim.x + threadIdx.x; i < n; i += (long)gridDim.x*blockDim.x)
        atomicAdd(&s[b[i]], 1);
    __syncthreads();
    for (int i = threadIdx.x; i < NGR; i += blockDim.x) if (s[i]) atomicAdd(&cnt[i], s[i]);
}

// split W1/W2 into bf16 hi/lo, transposed: g_w*h[n*CN+k] = bf16split(W[k*CN+n])
__global__ void wconvert_kernel(const float* __restrict__ W1, const float* __restrict__ W2) {
    int idx = blockIdx.x * 256 + threadIdx.x;   // 2*16384 total
    int sel = idx >> 14;
    int e   = idx & 16383;
    int k = e >> 7, nn = e & 127;
    const float* W = sel ? W2 : W1;
    float x = W[k*CN + nn];
    __nv_bfloat16 h = __float2bfloat16(x);
    __nv_bfloat16 l = __float2bfloat16(x - __bfloat162float(h));
    if (sel) { g_w2h[nn*CN+k] = h; g_w2l[nn*CN+k] = l; }
    else     { g_w1h[nn*CN+k] = h; g_w1l[nn*CN+k] = l; }
}

// ================= fused mma.sync GEMM + scatter =================
// C[64x128] = A_tile @ W via 3-term bf16-split mma.sync (AhWh + AlWh + AhWl).
// B tiles are K-SPLIT: only a 64-wide K-half of Bh/Bl is resident at a time,
// restaged mid-loop -> smem 65.5+KB total -> 3 blocks/SM (256 thr, 24 warps/SM).
template<int DEG, bool NORM>
__global__ __launch_bounds__(256, 3) void fused_mma_scatter(
    const float* __restrict__ A,
    const int* __restrict__ rows, const float* __restrict__ vals,
    float* __restrict__ agg,
    const int* __restrict__ batch, float* __restrict__ wb_out, int n)
{
    extern __shared__ char smem[];
    const uint32_t sb = smem_u32(smem);
    const int tid = threadIdx.x;
    const int wid = tid >> 5, lane = tid & 31;
    const int j0  = blockIdx.x * TM;
    const int nrow = min(TM, n - j0);

    const __nv_bfloat16* wth = NORM ? g_w2h : g_w1h;
    const __nv_bfloat16* wtl = NORM ? g_w2l : g_w1l;

    // ---- load A tile, (optional norm + output write), split to bf16 hi/lo
    {
        const float4* A4 = (const float4*)A;
        for (int i = tid; i < TM*32; i += 256) {
            int r = i >> 5, cq = i & 31;        // covers k = cq*4 .. cq*4+3
            float4 v = make_float4(0.f,0.f,0.f,0.f);
            if (r < nrow) {
                long idx = (long)(j0 + r) * 32 + cq;
                v = __ldcs(&A4[idx]);
                if (NORM) {
                    int g = batch[j0 + r];
                    float4 a = ((const float4*)g_scale1)[g*32 + cq];
                    float4 b = ((const float4*)g_shift1)[g*32 + cq];
                    v.x = v.x*a.x + b.x; v.y = v.y*a.y + b.y;
                    v.z = v.z*a.z + b.z; v.w = v.w*a.w + b.w;
                }
                __stcs(&((float4*)wb_out)[idx], v);
            }
            __nv_bfloat16 h0=__float2bfloat16(v.x), h1=__float2bfloat16(v.y),
                          h2=__float2bfloat16(v.z), h3=__float2bfloat16(v.w);
            __nv_bfloat16 l0=__float2bfloat16(v.x-__bfloat162float(h0)),
                          l1=__float2bfloat16(v.y-__bfloat162float(h1)),
                          l2=__float2bfloat16(v.z-__bfloat162float(h2)),
                          l3=__float2bfloat16(v.w-__bfloat162float(h3));
            uint2 hw = make_uint2((uint32_t)bfbits(h0) | ((uint32_t)bfbits(h1)<<16),
                                  (uint32_t)bfbits(h2) | ((uint32_t)bfbits(h3)<<16));
            uint2 lw = make_uint2((uint32_t)bfbits(l0) | ((uint32_t)bfbits(l1)<<16),
                                  (uint32_t)bfbits(l2) | ((uint32_t)bfbits(l3)<<16));
            uint32_t off = swzA(r, cq >> 1) + (uint32_t)(cq & 1) * 8;
            *(uint2*)(smem + OFF_AH + off) = hw;
            *(uint2*)(smem + OFF_AL + off) = lw;
        }
    }
    // ---- stage B K-half 0 (k = 0..63) of W^T hi/lo
    for (int i = tid; i < CN*8; i += 256) {
        int nn = i >> 3, q = i & 7;            // q = 16B chunk in 128B row
        uint32_t off = swzB(nn, q);
        *(uint4*)(smem + OFF_BH + off) = *(const uint4*)&wth[nn*CN + q*8];
        *(uint4*)(smem + OFF_BL + off) = *(const uint4*)&wtl[nn*CN + q*8];
    }
    // ---- stage scatter metadata
    int*   s_rows = (int*)(smem + OFF_META);
    float* s_vals = (float*)(smem + OFF_META + TM*DEG*4);
    for (int i = tid; i < nrow*DEG; i += 256) {
        long e = (long)j0*DEG + i;
        s_rows[i] = rows[e];
        s_vals[i] = vals[e];
    }
    __syncthreads();

    // ---- warp MMA: warp (wid&3) owns rows 16*(wid&3).., (wid>>2) owns 64-col half
    float acc[32];
#pragma unroll
    for (int i = 0; i < 32; i++) acc[i] = 0.f;
    {
        const int rgrp = (wid & 3) * 16;
        const int cgrp = (wid >> 2) * 64;
        const int sub = lane >> 3, l8 = lane & 7;
        const int ksub = sub >> 1;             // 0/1: +0 or +8 within a k16 step
        const int arow = rgrp + l8 + (sub & 1) * 8;
        const uint32_t aterm = (uint32_t)(arow * 256), ax = (uint32_t)(arow & 7);

#pragma unroll
        for (int half = 0; half < 2; half++) {
            if (half == 1) {
                __syncthreads();               // all warps done with B half 0
                for (int i = tid; i < CN*8; i += 256) {
                    int nn = i >> 3, q = i & 7;
                    uint32_t off = swzB(nn, q);
                    *(uint4*)(smem + OFF_BH + off) = *(const uint4*)&wth[nn*CN + 64 + q*8];
                    *(uint4*)(smem + OFF_BL + off) = *(const uint4*)&wtl[nn*CN + 64 + q*8];
                }
                __syncthreads();
            }
#pragma unroll
            for (int ks4 = 0; ks4 < 4; ks4++) {        // k16 step within half
                const int kk = half*4 + ks4;           // global k16 index
                const int achunk = 2*kk + ksub;        // A chunk 0..15
                uint32_t ah[4], al[4];
                ldm_x4(ah, sb + OFF_AH + aterm + (((uint32_t)achunk ^ ax) << 4));
                ldm_x4(al, sb + OFF_AL + aterm + (((uint32_t)achunk ^ ax) << 4));
                const int bchunk = 2*ks4 + ksub;       // B chunk 0..7 (within half)
#pragma unroll
                for (int np = 0; np < 4; np++) {       // n-tile: cols cgrp+16*np..+15
                    const int brow = cgrp + np*16 + l8 + (sub & 1) * 8;
                    uint32_t boff = (uint32_t)(brow * 128)
                                  + (((uint32_t)bchunk ^ (uint32_t)(brow & 7)) << 4);
                    uint32_t bh[4], bl[4];
                    ldm_x4(bh, sb + OFF_BH + boff);
                    ldm_x4(bl, sb + OFF_BL + boff);
                    float* d0 = &acc[(2*np+0)*4];
                    float* d1 = &acc[(2*np+1)*4];
                    mma_bf16(d0, ah, bh[0], bh[2]);
                    mma_bf16(d0, al, bh[0], bh[2]);
                    mma_bf16(d0, ah, bl[0], bl[2]);
                    mma_bf16(d1, ah, bh[1], bh[3]);
                    mma_bf16(d1, al, bh[1], bh[3]);
                    mma_bf16(d1, ah, bl[1], bl[3]);
                }
            }
        }
    }
    __syncthreads();   // A/B fully consumed -> C staging may overwrite

    // ---- write accumulators to smem C (fragment layout -> [row][col])
    float* Cs = (float*)(smem + OFF_CS);
    {
        const int rowt = (wid & 3)*16 + (lane >> 2);
        const int cbase = (wid >> 2)*64 + 2*(lane & 3);
#pragma unroll
        for (int nt = 0; nt < 8; nt++) {
            const int col = cbase + nt*8;
            *(float2*)&Cs[rowt*CSP + col]     = make_float2(acc[nt*4+0], acc[nt*4+1]);
            *(float2*)&Cs[(rowt+8)*CSP + col] = make_float2(acc[nt*4+2], acc[nt*4+3]);
        }
    }
    __syncthreads();

    // ---- scatter: one v4 global reduction per (entry, 4-channel group)
    const int total = nrow * DEG * 32;
    for (int idx = tid; idx < total; idx += 256) {
        int e = idx >> 5, q = idx & 31;
        int src = e / DEG;
        float v = s_vals[e];
        float4 y = *(const float4*)&Cs[src*CSP + q*4];
        float* p = agg + (long)s_rows[e]*CN + q*4;
        red4(p, v*y.x, v*y.y, v*y.z, v*y.w);
    }
}

// ================= GraphNorm stats / finalize / apply =================
__global__ void stats_kernel(const float* __restrict__ y, const int* __restrict__ batch,
                             int n, int which)
{
    float* sum = which ? g_sum2 : g_sum1;
    float* sq  = which ? g_sq2  : g_sq1;
    int c  = threadIdx.x & (CN-1);
    int p  = threadIdx.x >> 7;
    int r0 = blockIdx.x * SROWS;
    int rend = min(r0 + SROWS, n);
    float rs = 0.f, rq = 0.f;
    int cur = -1;
    for (int r = r0 + p; r < rend; r += 2) {
        int g = batch[r];
        if (g != cur) {
            if (cur >= 0) { atomicAdd(&sum[cur*CN+c], rs); atomicAdd(&sq[cur*CN+c], rq); }
            cur = g; rs = 0.f; rq = 0.f;
        }
        float v = y[(long)r*CN + c];
        rs += v; rq += v*v;
    }
    if (cur >= 0) { atomicAdd(&sum[cur*CN+c], rs); atomicAdd(&sq[cur*CN+c], rq); }
}

__global__ void finalize_kernel(const float* __restrict__ wgt, const float* __restrict__ bias,
                                const float* __restrict__ mscale, int which)
{
    int i = blockIdx.x*blockDim.x + threadIdx.x;
    if (i >= NGR*CN) return;
    const float* sum = which ? g_sum2 : g_sum1;
    const float* sq  = which ? g_sq2  : g_sq1;
    const int*   cnt = which ? g_cnt2 : g_cnt1;
    float* sc = which ? g_scale2 : g_scale1;
    float* sh = which ? g_shift2 : g_shift1;
    int g = i >> 7, c = i & (CN-1);
    float nf  = fmaxf((float)cnt[g], 1.f);
    float m   = sum[i] / nf;
    float ms  = m * mscale[c];
    float var = sq[i]/nf - 2.f*ms*m + ms*ms;
    float inv = rsqrtf(var + EPSV);
    float a   = wgt[c] * inv;
    sc[i] = a;
    sh[i] = bias[c] - ms * a;
}

__global__ void apply_norm_kernel(float* __restrict__ y, const int* __restrict__ batch, int n)
{
    long idx = (long)blockIdx.x*blockDim.x + threadIdx.x;
    if (idx >= (long)n*32) return;
    int r = (int)(idx >> 5); int cq = (int)(idx & 31);
    int g = batch[r];
    float4 v = ((float4*)y)[idx];
    float4 a = ((const float4*)g_scale2)[g*32+cq];
    float4 b = ((const float4*)g_shift2)[g*32+cq];
    v.x = v.x*a.x + b.x; v.y = v.y*a.y + b.y;
    v.z = v.z*a.z + b.z; v.w = v.w*a.w + b.w;
    ((float4*)y)[idx] = v;
}

// ================= launch =================
extern "C" void kernel_launch(void* const* d_in, const int* in_sizes, int n_in,
                              void* d_out, int out_size)
{
    const float* x0   = (const float*)d_in[0];
    const float* x1   = (const float*)d_in[1];
    const float* x2   = (const float*)d_in[2];
    const float* W1   = (const float*)d_in[3];
    const float* W2   = (const float*)d_in[4];
    const float* gn1w = (const float*)d_in[5];
    const float* gn1b = (const float*)d_in[6];
    const float* gn1m = (const float*)d_in[7];
    const float* gn2w = (const float*)d_in[8];
    const float* gn2b = (const float*)d_in[9];
    const float* gn2m = (const float*)d_in[10];
    const int*   i2r  = (const int*)d_in[11];
    const float* i2v  = (const float*)d_in[13];
    const int*   i1r  = (const int*)d_in[14];
    const float* i1v  = (const float*)d_in[16];
    const int*   bn   = (const int*)d_in[17];
    const int*   be   = (const int*)d_in[18];

    const int n0 = in_sizes[0] / CN;
    const int n1 = in_sizes[1] / CN;
    const int n2 = in_sizes[2] / CN;

    float* out_x0 = (float*)d_out;
    float* out_x1 = out_x0 + (size_t)n0 * CN;
    float* out_x2 = out_x1 + (size_t)n1 * CN;

    const int SM3 = OFF_META + TM*3*8;   // 67072
    const int SM2 = OFF_META + TM*2*8;   // 66560
    cudaFuncSetAttribute((const void*)fused_mma_scatter<3,false>,
                         cudaFuncAttributeMaxDynamicSharedMemorySize, SM3);
    cudaFuncSetAttribute((const void*)fused_mma_scatter<2,true>,
                         cudaFuncAttributeMaxDynamicSharedMemorySize, SM2);

    // residual pre-fill of outputs (x_2 copy fused into GEMM1's A-load)
    cudaMemcpyAsync(out_x0, x0, (size_t)n0*CN*sizeof(float), cudaMemcpyDeviceToDevice, 0);
    cudaMemcpyAsync(out_x1, x1, (size_t)n1*CN*sizeof(float), cudaMemcpyDeviceToDevice, 0);

    zero_stats_kernel<<<64, 256>>>();
    count_kernel<<<232, 256>>>(be, n1, 0);
    count_kernel<<<232, 256>>>(bn, n0, 1);
    wconvert_kernel<<<128, 256>>>(W1, W2);

    // layer 1: out_x1 += inc2 @ (x_2 @ W1); out_x2 = x_2 (fused copy)
    fused_mma_scatter<3,false><<<(n2+TM-1)/TM, 256, SM3>>>(
        x2, i2r, i2v, out_x1, nullptr, out_x2, n2);
    stats_kernel<<<(n1+SROWS-1)/SROWS, 256>>>(out_x1, be, n1, 0);
    finalize_kernel<<<64, 256>>>(gn1w, gn1b, gn1m, 0);

    // layer 2: normalize x_1_out in-flight, out_x0 += inc1 @ (x_1_out @ W2)
    fused_mma_scatter<2,true><<<(n1+TM-1)/TM, 256, SM2>>>(
        out_x1, i1r, i1v, out_x0, be, out_x1, n1);
    stats_kernel<<<(n0+SROWS-1)/SROWS, 256>>>(out_x0, bn, n0, 1);
    finalize_kernel<<<64, 256>>>(gn2w, gn2b, gn2m, 1);
    apply_norm_kernel<<<(int)(((long)n0*32 + 255)/256), 256>>>(out_x0, bn, n0);
}